// round 2
// baseline (speedup 1.0000x reference)
#include <cuda_runtime.h>

// Fixed problem shapes
#define TT 4
#define BB 512
#define GG 16
#define NN 256
#define DD 32
#define NPAD 257
#define NEG_BIG_F (-1e30f)

// Global accumulators: zwl, zpl, pl(sum cos*w, negated at end), ol, nobj
__device__ double g_acc[5];
__device__ unsigned int g_count;   // zero-initialized; reset by last block

__global__ __launch_bounds__(256, 2) void losses_kernel(
    const float* __restrict__ z_what,
    const float* __restrict__ z_pres_prob,
    const float* __restrict__ z_pres,
    const float* __restrict__ base_losses,
    const void*  __restrict__ step_ptr,
    float* __restrict__ out, int out_size)
{
    const int blk = blockIdx.x;
    const int t = blk >> 9;            // / BB
    const int b = blk & (BB - 1);
    const int tid  = threadIdx.x;
    const int n    = tid;              // one thread per grid cell
    const int i    = n >> 4, j = n & 15;

    extern __shared__ float sm[];
    float* s_wb  = sm;                 // [DD][NPAD] z_what at t+1, d-major
    float* s_hm  = sm + DD * NPAD;     // [DD][NPAD] horizontal max of weighted |wa|
    float* s_pb  = sm + 2 * DD * NPAD; // [NN] prob at t+1
    float* s_nb  = s_pb + NN;          // [NN] ||z_what[t+1][:,m]||
    float* s_red = s_nb + NN;          // 40 floats reduction scratch

    const size_t slice = (size_t)NN * DD;
    const float* ga = z_what + (((size_t)t * BB + b) * NN + n) * DD;       // own column @ t
    const float* gb = ga + (size_t)BB * slice;                              // own column @ t+1

    // ---- load own columns into registers (coalesced-over-iters float4) ----
    float pr[DD], wbr[DD];
    float zwl = 0.f, nb2 = 0.f, pn2 = 0.f, dotc = 0.f;
    {
        const float4* ga4 = (const float4*)ga;
        const float4* gb4 = (const float4*)gb;
        #pragma unroll
        for (int k = 0; k < DD / 4; ++k) {
            float4 va = ga4[k];
            float4 vb = gb4[k];
            pr[4*k+0] = va.x; pr[4*k+1] = va.y; pr[4*k+2] = va.z; pr[4*k+3] = va.w;
            wbr[4*k+0] = vb.x; wbr[4*k+1] = vb.y; wbr[4*k+2] = vb.z; wbr[4*k+3] = vb.w;
        }
        #pragma unroll
        for (int d = 0; d < DD; ++d) {
            float dv = wbr[d] - pr[d];
            zwl  += dv * dv;
            nb2  += wbr[d] * wbr[d];
            pn2  += pr[d] * pr[d];
            dotc += pr[d] * wbr[d];
            s_wb[d * NPAD + n] = wbr[d];     // transpose store
        }
    }
    const float nbn = sqrtf(nb2);
    s_nb[n] = nbn;

    const float pa_n = z_pres_prob[((size_t)t * BB + b) * NN + n];
    const float pb_n = z_pres_prob[((size_t)(t + 1) * BB + b) * NN + n];
    s_pb[n] = pb_n;

    // ---- pool pass 1: horizontal 3-max of w = |pr|*pa via warp shuffles ----
    #pragma unroll
    for (int d = 0; d < DD; ++d) {
        float wv = fabsf(pr[d]) * pa_n;
        float l = __shfl_up_sync(0xffffffffu, wv, 1);
        float r = __shfl_down_sync(0xffffffffu, wv, 1);
        float hm = wv;
        if (j > 0)  hm = fmaxf(hm, l);
        if (j < 15) hm = fmaxf(hm, r);
        s_hm[d * NPAD + n] = hm;
    }

    // ---- z_pres loss (t = 0,1 only) — overlap latency with the sync ----
    float zpl = 0.f;
    if (t < TT - 2) {
        const float* zp = z_pres + ((size_t)t * BB + b) * NN + n;
        float p0 = zp[0];
        float p1 = zp[(size_t)BB * NN];
        float p2 = zp[2 * (size_t)BB * NN];
        float sim = 1.f - (p2 - p0) * (p2 - p0);
        float del = (p2 - p1) * (p2 - p1) + (p0 - p1) * (p0 - p1);
        zpl = sim * del;
    }
    __syncthreads();

    // ---- pool pass 2: vertical 3-max + cosine parts ----
    float dotp = 0.f, na2 = 0.f;
    const bool up_ok = (i > 0), dn_ok = (i < 15);
    #pragma unroll
    for (int d = 0; d < DD; ++d) {
        const float* row = s_hm + d * NPAD;
        float am = row[n];
        if (up_ok) am = fmaxf(am, row[n - 16]);
        if (dn_ok) am = fmaxf(am, row[n + 16]);
        float bv = fabsf(wbr[d]);
        dotp += am * bv;
        na2  += am * am;
    }
    // dot = pbn * dotp ; ||b|| = pbn * nbn ; ||a|| = sqrt(na2)
    float cosim = (dotp * pb_n) / fmaxf(sqrtf(na2) * (pb_n * nbn), 1e-6f);
    float plp = cosim * 0.5f * (pa_n + pb_n);     // pool_loss = -sum(plp)

    // ---- objects loss: 9 wrapped-neighbor cosines ----
    const float prior_n = sqrtf(pn2);
    float sum_sim = 0.f, max_sim = NEG_BIG_F;
    bool any = false;
    // center (m == n): everything in registers
    if (pb_n > 0.5f) {
        float s = dotc / fmaxf(prior_n * nbn, 1e-8f);
        sum_sim += s; max_sim = fmaxf(max_sim, s); any = true;
    }
    #pragma unroll
    for (int q = 0; q < 9; ++q) {
        if (q == 4) continue;  // center done
        const int di = q / 3 - 1, dj = q % 3 - 1;
        const int m = (((i + di) & 15) << 4) | ((j + dj) & 15);
        if (s_pb[m] > 0.5f) {
            const float* col = s_wb + m;
            float dp = 0.f;
            #pragma unroll
            for (int d = 0; d < DD; ++d)
                dp += pr[d] * col[d * NPAD];
            float s = dp / fmaxf(prior_n * s_nb[m], 1e-8f);
            sum_sim += s; max_sim = fmaxf(max_sim, s); any = true;
        }
    }
    bool detected = pa_n > 0.5f;
    float olp  = (detected && any) ? (sum_sim - 5.f * max_sim) : 0.f;
    float nobj = detected ? 1.f : 0.f;

    // ---- block reduce + global accumulate ----
    float vals[5] = {zwl, zpl, plp, olp, nobj};
    #pragma unroll
    for (int k = 0; k < 5; ++k) {
        float v = vals[k];
        #pragma unroll
        for (int o = 16; o > 0; o >>= 1) v += __shfl_down_sync(0xffffffffu, v, o);
        vals[k] = v;
    }
    int lane = tid & 31, w = tid >> 5;
    if (lane == 0) {
        #pragma unroll
        for (int k = 0; k < 5; ++k) s_red[w * 5 + k] = vals[k];
    }
    __syncthreads();
    if (tid == 0) {
        #pragma unroll
        for (int k = 0; k < 5; ++k) {
            float s = 0.f;
            #pragma unroll
            for (int wq = 0; wq < 8; ++wq) s += s_red[wq * 5 + k];
            atomicAdd(&g_acc[k], (double)s);
        }
        __threadfence();
        unsigned ticket = atomicAdd(&g_count, 1u);
        if (ticket == gridDim.x - 1) {
            // all blocks' accumulations are visible (fence + ticket ordering)
            double a0 = atomicAdd(&g_acc[0], 0.0);
            double a1 = atomicAdd(&g_acc[1], 0.0);
            double a2 = atomicAdd(&g_acc[2], 0.0);
            double a3 = atomicAdd(&g_acc[3], 0.0);
            double a4 = atomicAdd(&g_acc[4], 0.0);
            float zwlT = (float)a0, zplT = (float)a1;
            float plT  = -(float)a2, olT = (float)a3, nobjT = (float)a4;
            float bsum = base_losses[0] + base_losses[1] + base_losses[2] + base_losses[3];
            int iv = *(const int*)step_ptr;
            float gs = (iv >= 0 && iv < 1000000000) ? (float)iv : *(const float*)step_ptr;
            float scaling = fminf(1.f, gs / 300000.f);
            float loss = bsum + zwlT * 10.f + zplT + plT + olT * scaling * 10.f;
            float res[6] = {loss, zwlT, zplT, plT, olT, nobjT};
            for (int k = 0; k < 6 && k < out_size; ++k) out[k] = res[k];
            __threadfence();
            // reset for next graph replay
            g_acc[0] = 0.0; g_acc[1] = 0.0; g_acc[2] = 0.0;
            g_acc[3] = 0.0; g_acc[4] = 0.0;
            g_count = 0u;
        }
    }
}

extern "C" void kernel_launch(void* const* d_in, const int* in_sizes, int n_in,
                              void* d_out, int out_size) {
    const float* z_what      = (const float*)d_in[0];
    const float* z_pres_prob = (const float*)d_in[1];
    const float* z_pres      = (const float*)d_in[2];
    const float* base_losses = (const float*)d_in[3];
    const void*  gstep       = d_in[4];

    const size_t SMEM = (size_t)(2 * DD * NPAD + 2 * NN + 64) * sizeof(float); // ~68 KB
    static int smem_set = 0;
    if (!smem_set) {
        cudaFuncSetAttribute(losses_kernel, cudaFuncAttributeMaxDynamicSharedMemorySize, (int)SMEM);
        smem_set = 1;
    }
    losses_kernel<<<(TT - 1) * BB, 256, SMEM>>>(z_what, z_pres_prob, z_pres,
                                                base_losses, gstep,
                                                (float*)d_out, out_size);
}

// round 3
// speedup vs baseline: 1.3022x; 1.3022x over previous
#include <cuda_runtime.h>

// Fixed problem shapes
#define TT 4
#define BB 512
#define GG 16
#define NN 256
#define DD 32
#define PADW 36          // words per smem row (144B): conflict-free for .128 access
#define NEG_BIG_F (-1e30f)

// Global accumulators: zwl, zpl, pl(sum cos*w, negated at end), ol, nobj
__device__ double g_acc[5];
__device__ unsigned int g_count;   // zero-init; reset by last block each replay

__global__ __launch_bounds__(256, 3) void losses_kernel(
    const float* __restrict__ z_what,
    const float* __restrict__ z_pres_prob,
    const float* __restrict__ z_pres,
    const float* __restrict__ base_losses,
    const void*  __restrict__ step_ptr,
    float* __restrict__ out, int out_size)
{
    const int blk = blockIdx.x;
    const int t = blk >> 9;            // / BB
    const int b = blk & (BB - 1);
    const int tid = threadIdx.x;
    const int n   = tid;               // one thread per grid cell
    const int i   = n >> 4, j = n & 15;

    extern __shared__ float sm[];
    float* s_wa  = sm;                  // [NN][PADW] z_what @ t  (later aliased as hmax)
    float* s_wb  = sm + NN * PADW;      // [NN][PADW] z_what @ t+1
    float* s_pb  = sm + 2 * NN * PADW;  // [NN] prob @ t+1
    float* s_nb  = s_pb + NN;           // [NN] ||z_what[t+1][m]||
    float* s_red = s_nb + NN;           // 40 floats
    float* s_hm  = s_wa;                // alias: horizontal max rows (own-row only before overwrite)

    const size_t slice = (size_t)NN * DD;
    const float4* ga4 = (const float4*)(z_what + ((size_t)t * BB + b) * slice);
    const float4* gb4 = (const float4*)((const float*)ga4 + (size_t)BB * slice);

    // ---- coalesced load of both slices, transpose to [n][d] rows, fuse zwl ----
    float zwl = 0.f;
    #pragma unroll
    for (int it = 0; it < (NN * DD / 4) / 256; ++it) {   // 8 iters
        int k4 = it * 256 + tid;
        float4 va = ga4[k4];
        float4 vb = gb4[k4];
        int nn = k4 >> 3;            // 8 float4 per cell (D=32)
        int d0 = (k4 & 7) * 4;
        float dx = vb.x - va.x, dy = vb.y - va.y, dz = vb.z - va.z, dw = vb.w - va.w;
        zwl += dx*dx + dy*dy + dz*dz + dw*dw;
        *(float4*)(s_wa + nn * PADW + d0) = va;
        *(float4*)(s_wb + nn * PADW + d0) = vb;
    }
    const float pa_n = z_pres_prob[((size_t)t * BB + b) * NN + n];
    const float pb_n = z_pres_prob[((size_t)(t + 1) * BB + b) * NN + n];
    s_pb[n] = pb_n;

    // ---- z_pres loss (t = 0,1 windows only) ----
    float zpl = 0.f;
    if (t < TT - 2) {
        const float* zp = z_pres + ((size_t)t * BB + b) * NN + n;
        float p0 = zp[0];
        float p1 = zp[(size_t)BB * NN];
        float p2 = zp[2 * (size_t)BB * NN];
        float sim = 1.f - (p2 - p0) * (p2 - p0);
        float del = (p2 - p1) * (p2 - p1) + (p0 - p1) * (p0 - p1);
        zpl = sim * del;
    }
    __syncthreads();

    // ---- own rows: prior (registers) + t+1 stats ----
    float pr[DD];
    float pn2 = 0.f, nb2 = 0.f, dotc = 0.f;
    {
        const float* rowa = s_wa + n * PADW;
        const float* rowb = s_wb + n * PADW;
        #pragma unroll
        for (int k = 0; k < DD / 4; ++k) {
            float4 a = *(const float4*)(rowa + 4 * k);
            float4 bv = *(const float4*)(rowb + 4 * k);
            pr[4*k+0] = a.x; pr[4*k+1] = a.y; pr[4*k+2] = a.z; pr[4*k+3] = a.w;
            pn2 += a.x*a.x + a.y*a.y + a.z*a.z + a.w*a.w;
            nb2 += bv.x*bv.x + bv.y*bv.y + bv.z*bv.z + bv.w*bv.w;
            dotc += a.x*bv.x + a.y*bv.y + a.z*bv.z + a.w*bv.w;
        }
    }
    const float nbn = sqrtf(nb2);
    s_nb[n] = nbn;

    // ---- pool pass 1: horizontal 3-max of |pr|*pa via lane shuffles,
    //      write own hm row (overwrites own s_wa row — same-thread, safe) ----
    {
        const bool lok = (j > 0), rok = (j < 15);
        float* rowh = s_hm + n * PADW;
        #pragma unroll
        for (int k = 0; k < DD / 4; ++k) {
            float4 h;
            #pragma unroll
            for (int c = 0; c < 4; ++c) {
                int d = 4 * k + c;
                float wv = fabsf(pr[d]) * pa_n;
                float l = __shfl_up_sync(0xffffffffu, wv, 1);
                float r = __shfl_down_sync(0xffffffffu, wv, 1);
                float hm = wv;
                if (lok) hm = fmaxf(hm, l);
                if (rok) hm = fmaxf(hm, r);
                ((float*)&h)[c] = hm;
            }
            *(float4*)(rowh + 4 * k) = h;
        }
    }
    __syncthreads();

    // ---- pool pass 2: vertical 3-max + cosine accumulation ----
    float dotp = 0.f, na2 = 0.f;
    {
        const float* r0 = s_hm + n * PADW;
        const float* ru = (i > 0)  ? (r0 - 16 * PADW) : r0;
        const float* rd = (i < 15) ? (r0 + 16 * PADW) : r0;
        const float* rb = s_wb + n * PADW;
        #pragma unroll
        for (int k = 0; k < DD / 4; ++k) {
            float4 h0 = *(const float4*)(r0 + 4 * k);
            float4 hu = *(const float4*)(ru + 4 * k);
            float4 hd = *(const float4*)(rd + 4 * k);
            float4 bv = *(const float4*)(rb + 4 * k);
            float a0 = fmaxf(h0.x, fmaxf(hu.x, hd.x));
            float a1 = fmaxf(h0.y, fmaxf(hu.y, hd.y));
            float a2 = fmaxf(h0.z, fmaxf(hu.z, hd.z));
            float a3 = fmaxf(h0.w, fmaxf(hu.w, hd.w));
            dotp += a0*fabsf(bv.x) + a1*fabsf(bv.y) + a2*fabsf(bv.z) + a3*fabsf(bv.w);
            na2  += a0*a0 + a1*a1 + a2*a2 + a3*a3;
        }
    }
    float cosim = (dotp * pb_n) / fmaxf(sqrtf(na2) * (pb_n * nbn), 1e-6f);
    float plp = cosim * 0.5f * (pa_n + pb_n);     // pool_loss = -sum(plp)

    // ---- objects loss: 9 wrapped-neighbor cosines (center from registers) ----
    const float prior_n = sqrtf(pn2);
    float sum_sim = 0.f, max_sim = NEG_BIG_F;
    bool any = false;
    if (pb_n > 0.5f) {
        float s = dotc / fmaxf(prior_n * nbn, 1e-8f);
        sum_sim += s; max_sim = fmaxf(max_sim, s); any = true;
    }
    #pragma unroll
    for (int q = 0; q < 9; ++q) {
        if (q == 4) continue;
        const int di = q / 3 - 1, dj = q % 3 - 1;
        const int m = (((i + di) & 15) << 4) | ((j + dj) & 15);
        if (s_pb[m] > 0.5f) {
            const float* row = s_wb + m * PADW;
            float dp = 0.f;
            #pragma unroll
            for (int k = 0; k < DD / 4; ++k) {
                float4 v = *(const float4*)(row + 4 * k);
                dp += pr[4*k+0]*v.x + pr[4*k+1]*v.y + pr[4*k+2]*v.z + pr[4*k+3]*v.w;
            }
            float s = dp / fmaxf(prior_n * s_nb[m], 1e-8f);
            sum_sim += s; max_sim = fmaxf(max_sim, s); any = true;
        }
    }
    bool detected = pa_n > 0.5f;
    float olp  = (detected && any) ? (sum_sim - 5.f * max_sim) : 0.f;
    float nobj = detected ? 1.f : 0.f;

    // ---- block reduce + global accumulate ----
    float vals[5] = {zwl, zpl, plp, olp, nobj};
    #pragma unroll
    for (int k = 0; k < 5; ++k) {
        float v = vals[k];
        #pragma unroll
        for (int o = 16; o > 0; o >>= 1) v += __shfl_down_sync(0xffffffffu, v, o);
        vals[k] = v;
    }
    int lane = tid & 31, w = tid >> 5;
    if (lane == 0) {
        #pragma unroll
        for (int k = 0; k < 5; ++k) s_red[w * 5 + k] = vals[k];
    }
    __syncthreads();
    if (tid == 0) {
        #pragma unroll
        for (int k = 0; k < 5; ++k) {
            float s = 0.f;
            #pragma unroll
            for (int wq = 0; wq < 8; ++wq) s += s_red[wq * 5 + k];
            atomicAdd(&g_acc[k], (double)s);
        }
        __threadfence();
        unsigned ticket = atomicAdd(&g_count, 1u);
        if (ticket == gridDim.x - 1) {
            double a0 = atomicAdd(&g_acc[0], 0.0);
            double a1 = atomicAdd(&g_acc[1], 0.0);
            double a2 = atomicAdd(&g_acc[2], 0.0);
            double a3 = atomicAdd(&g_acc[3], 0.0);
            double a4 = atomicAdd(&g_acc[4], 0.0);
            float zwlT = (float)a0, zplT = (float)a1;
            float plT  = -(float)a2, olT = (float)a3, nobjT = (float)a4;
            float bsum = base_losses[0] + base_losses[1] + base_losses[2] + base_losses[3];
            int iv = *(const int*)step_ptr;
            float gs = (iv >= 0 && iv < 1000000000) ? (float)iv : *(const float*)step_ptr;
            float scaling = fminf(1.f, gs / 300000.f);
            float loss = bsum + zwlT * 10.f + zplT + plT + olT * scaling * 10.f;
            float res[6] = {loss, zwlT, zplT, plT, olT, nobjT};
            for (int k = 0; k < 6 && k < out_size; ++k) out[k] = res[k];
            __threadfence();
            g_acc[0] = 0.0; g_acc[1] = 0.0; g_acc[2] = 0.0;
            g_acc[3] = 0.0; g_acc[4] = 0.0;
            g_count = 0u;
        }
    }
}

extern "C" void kernel_launch(void* const* d_in, const int* in_sizes, int n_in,
                              void* d_out, int out_size) {
    const float* z_what      = (const float*)d_in[0];
    const float* z_pres_prob = (const float*)d_in[1];
    const float* z_pres      = (const float*)d_in[2];
    const float* base_losses = (const float*)d_in[3];
    const void*  gstep       = d_in[4];

    const size_t SMEM = (size_t)(2 * NN * PADW + 2 * NN + 40) * sizeof(float); // ~74.2 KB
    static int smem_set = 0;
    if (!smem_set) {
        cudaFuncSetAttribute(losses_kernel, cudaFuncAttributeMaxDynamicSharedMemorySize, (int)SMEM);
        smem_set = 1;
    }
    losses_kernel<<<(TT - 1) * BB, 256, SMEM>>>(z_what, z_pres_prob, z_pres,
                                                base_losses, gstep,
                                                (float*)d_out, out_size);
}

// round 4
// speedup vs baseline: 1.8978x; 1.4574x over previous
#include <cuda_runtime.h>
#include <cuda_fp16.h>

// Fixed problem shapes
#define TT 4
#define BB 512
#define GG 16
#define NN 256
#define DD 32
#define PADH 40          // halves per smem row (80B = 20 words, 20 ≡ 4 mod 8 -> conflict-free .128)
#define NEG_BIG_F (-1e30f)

__device__ double g_acc[5];        // zwl, zpl, pl(sum cos*w), ol, nobj
__device__ unsigned int g_count;   // zero-init; reset by last block each replay

__device__ __forceinline__ unsigned h2u(half2 h) { return *reinterpret_cast<unsigned*>(&h); }
__device__ __forceinline__ half2    u2h(unsigned u) { return *reinterpret_cast<half2*>(&u); }

__global__ __launch_bounds__(256, 4) void losses_kernel(
    const float* __restrict__ z_what,
    const float* __restrict__ z_pres_prob,
    const float* __restrict__ z_pres,
    const float* __restrict__ base_losses,
    const void*  __restrict__ step_ptr,
    float* __restrict__ out, int out_size)
{
    const int blk = blockIdx.x;
    const int t = blk >> 9;            // / BB
    const int b = blk & (BB - 1);
    const int tid = threadIdx.x;
    const int n   = tid;               // one thread per grid cell
    const int i   = n >> 4, j = n & 15;

    extern __shared__ char smraw[];
    half*  s_wa = (half*)smraw;                     // [NN][PADH] z_what @ t (fp16) -> aliased as hmax
    half*  s_wb = s_wa + NN * PADH;                 // [NN][PADH] z_what @ t+1 (fp16)
    float* s_pb = (float*)(smraw + (size_t)2 * NN * PADH * sizeof(half));
    float* s_nb = s_pb + NN;                        // ||z_what[t+1][m]|| (fp16-consistent)
    float* s_red = s_nb + NN;                       // 40 floats

    const size_t slice = (size_t)NN * DD;
    const float4* ga4 = (const float4*)(z_what + ((size_t)t * BB + b) * slice);
    const float4* gb4 = (const float4*)((const float*)ga4 + (size_t)BB * slice);

    // ---- coalesced global load; zwl in fp32 (exact); stage fp16 transposed rows ----
    float zwl = 0.f;
    #pragma unroll
    for (int it = 0; it < 8; ++it) {
        int k4 = it * 256 + tid;
        float4 va = ga4[k4];
        float4 vb = gb4[k4];
        int nn = k4 >> 3;            // cell
        int d0 = (k4 & 7) * 4;       // first d of this fragment
        float dx = vb.x - va.x, dy = vb.y - va.y, dz = vb.z - va.z, dw = vb.w - va.w;
        zwl += dx*dx + dy*dy + dz*dz + dw*dw;
        half2 a0 = __floats2half2_rn(va.x, va.y), a1 = __floats2half2_rn(va.z, va.w);
        half2 b0 = __floats2half2_rn(vb.x, vb.y), b1 = __floats2half2_rn(vb.z, vb.w);
        *(uint2*)(s_wa + nn * PADH + d0) = make_uint2(h2u(a0), h2u(a1));
        *(uint2*)(s_wb + nn * PADH + d0) = make_uint2(h2u(b0), h2u(b1));
    }
    const float pa_n = z_pres_prob[((size_t)t * BB + b) * NN + n];
    const float pb_n = z_pres_prob[((size_t)(t + 1) * BB + b) * NN + n];
    s_pb[n] = pb_n;

    // ---- z_pres loss (t = 0,1 windows only), overlap with barrier ----
    float zpl = 0.f;
    if (t < TT - 2) {
        const float* zp = z_pres + ((size_t)t * BB + b) * NN + n;
        float p0 = zp[0];
        float p1 = zp[(size_t)BB * NN];
        float p2 = zp[2 * (size_t)BB * NN];
        float sim = 1.f - (p2 - p0) * (p2 - p0);
        float del = (p2 - p1) * (p2 - p1) + (p0 - p1) * (p0 - p1);
        zpl = sim * del;
    }
    __syncthreads();

    // ---- own rows: pr (half2 regs), norms + center dot in fp32 ----
    half2 pr2[16];
    float pn2 = 0.f, nb2 = 0.f, dotc = 0.f;
    {
        const uint4* ra = (const uint4*)(s_wa + n * PADH);
        const uint4* rb = (const uint4*)(s_wb + n * PADH);
        #pragma unroll
        for (int k = 0; k < 4; ++k) {
            uint4 qa = ra[k], qb = rb[k];
            unsigned ua[4] = {qa.x, qa.y, qa.z, qa.w};
            unsigned ub[4] = {qb.x, qb.y, qb.z, qb.w};
            #pragma unroll
            for (int c = 0; c < 4; ++c) {
                half2 ha = u2h(ua[c]);
                pr2[4 * k + c] = ha;
                float2 fa = __half22float2(ha);
                float2 fb = __half22float2(u2h(ub[c]));
                pn2  += fa.x * fa.x + fa.y * fa.y;
                nb2  += fb.x * fb.x + fb.y * fb.y;
                dotc += fa.x * fb.x + fa.y * fb.y;
            }
        }
    }
    const float nbn = sqrtf(nb2);
    s_nb[n] = nbn;

    // ---- pool pass 1: horizontal 3-max of |pr|*pa in half2, own row overwrite (safe) ----
    {
        const half2 pa2 = __float2half2_rn(pa_n);
        const bool lok = (j > 0), rok = (j < 15);
        uint4* rowh = (uint4*)(s_wa + n * PADH);
        #pragma unroll
        for (int k4o = 0; k4o < 4; ++k4o) {
            unsigned hv[4];
            #pragma unroll
            for (int c = 0; c < 4; ++c) {
                half2 wv = __hmul2(__habs2(pr2[4 * k4o + c]), pa2);
                unsigned w = h2u(wv);
                unsigned l = __shfl_up_sync(0xffffffffu, w, 1);
                unsigned r = __shfl_down_sync(0xffffffffu, w, 1);
                half2 hm = wv;
                if (lok) hm = __hmax2(hm, u2h(l));
                if (rok) hm = __hmax2(hm, u2h(r));
                hv[c] = h2u(hm);
            }
            rowh[k4o] = make_uint4(hv[0], hv[1], hv[2], hv[3]);
        }
    }
    __syncthreads();

    // ---- pool pass 2: vertical 3-max + cosine accumulation (fp32 accum) ----
    float dotp = 0.f, na2 = 0.f;
    {
        const uint4* r0 = (const uint4*)(s_wa + n * PADH);
        const uint4* ru = (i > 0)  ? (const uint4*)(s_wa + (n - 16) * PADH) : r0;
        const uint4* rd = (i < 15) ? (const uint4*)(s_wa + (n + 16) * PADH) : r0;
        const uint4* rb = (const uint4*)(s_wb + n * PADH);
        #pragma unroll
        for (int k = 0; k < 4; ++k) {
            uint4 q0 = r0[k], qu = ru[k], qd = rd[k], qb = rb[k];
            unsigned u0[4] = {q0.x, q0.y, q0.z, q0.w};
            unsigned uu[4] = {qu.x, qu.y, qu.z, qu.w};
            unsigned ud[4] = {qd.x, qd.y, qd.z, qd.w};
            unsigned ub[4] = {qb.x, qb.y, qb.z, qb.w};
            #pragma unroll
            for (int c = 0; c < 4; ++c) {
                half2 m = __hmax2(u2h(u0[c]), __hmax2(u2h(uu[c]), u2h(ud[c])));
                float2 am = __half22float2(m);
                float2 bv = __half22float2(__habs2(u2h(ub[c])));
                dotp += am.x * bv.x + am.y * bv.y;
                na2  += am.x * am.x + am.y * am.y;
            }
        }
    }
    float cosim = (dotp * pb_n) / fmaxf(sqrtf(na2) * (pb_n * nbn), 1e-6f);
    float plp = cosim * 0.5f * (pa_n + pb_n);     // pool_loss = -sum(plp)

    // ---- objects loss: 9 wrapped-neighbor cosines (center from registers) ----
    const float prior_n = sqrtf(pn2);
    float sum_sim = 0.f, max_sim = NEG_BIG_F;
    bool any = false;
    if (pb_n > 0.5f) {
        float s = dotc / fmaxf(prior_n * nbn, 1e-8f);
        sum_sim += s; max_sim = fmaxf(max_sim, s); any = true;
    }
    #pragma unroll
    for (int q = 0; q < 9; ++q) {
        if (q == 4) continue;
        const int di = q / 3 - 1, dj = q % 3 - 1;
        const int m = (((i + di) & 15) << 4) | ((j + dj) & 15);
        if (s_pb[m] > 0.5f) {
            const uint4* rn = (const uint4*)(s_wb + m * PADH);
            float dp = 0.f;
            #pragma unroll
            for (int k = 0; k < 4; ++k) {
                uint4 qv = rn[k];
                unsigned uv[4] = {qv.x, qv.y, qv.z, qv.w};
                #pragma unroll
                for (int c = 0; c < 4; ++c) {
                    float2 fb = __half22float2(u2h(uv[c]));
                    float2 fa = __half22float2(pr2[4 * k + c]);
                    dp += fa.x * fb.x + fa.y * fb.y;
                }
            }
            float s = dp / fmaxf(prior_n * s_nb[m], 1e-8f);
            sum_sim += s; max_sim = fmaxf(max_sim, s); any = true;
        }
    }
    bool detected = pa_n > 0.5f;
    float olp  = (detected && any) ? (sum_sim - 5.f * max_sim) : 0.f;
    float nobj = detected ? 1.f : 0.f;

    // ---- block reduce + global accumulate ----
    float vals[5] = {zwl, zpl, plp, olp, nobj};
    #pragma unroll
    for (int k = 0; k < 5; ++k) {
        float v = vals[k];
        #pragma unroll
        for (int o = 16; o > 0; o >>= 1) v += __shfl_down_sync(0xffffffffu, v, o);
        vals[k] = v;
    }
    int lane = tid & 31, w = tid >> 5;
    if (lane == 0) {
        #pragma unroll
        for (int k = 0; k < 5; ++k) s_red[w * 5 + k] = vals[k];
    }
    __syncthreads();
    if (tid == 0) {
        #pragma unroll
        for (int k = 0; k < 5; ++k) {
            float s = 0.f;
            #pragma unroll
            for (int wq = 0; wq < 8; ++wq) s += s_red[wq * 5 + k];
            atomicAdd(&g_acc[k], (double)s);
        }
        __threadfence();
        unsigned ticket = atomicAdd(&g_count, 1u);
        if (ticket == gridDim.x - 1) {
            double a0 = atomicAdd(&g_acc[0], 0.0);
            double a1 = atomicAdd(&g_acc[1], 0.0);
            double a2 = atomicAdd(&g_acc[2], 0.0);
            double a3 = atomicAdd(&g_acc[3], 0.0);
            double a4 = atomicAdd(&g_acc[4], 0.0);
            float zwlT = (float)a0, zplT = (float)a1;
            float plT  = -(float)a2, olT = (float)a3, nobjT = (float)a4;
            float bsum = base_losses[0] + base_losses[1] + base_losses[2] + base_losses[3];
            int iv = *(const int*)step_ptr;
            float gs = (iv >= 0 && iv < 1000000000) ? (float)iv : *(const float*)step_ptr;
            float scaling = fminf(1.f, gs / 300000.f);
            float loss = bsum + zwlT * 10.f + zplT + plT + olT * scaling * 10.f;
            float res[6] = {loss, zwlT, zplT, plT, olT, nobjT};
            for (int k = 0; k < 6 && k < out_size; ++k) out[k] = res[k];
            __threadfence();
            g_acc[0] = 0.0; g_acc[1] = 0.0; g_acc[2] = 0.0;
            g_acc[3] = 0.0; g_acc[4] = 0.0;
            g_count = 0u;
        }
    }
}

extern "C" void kernel_launch(void* const* d_in, const int* in_sizes, int n_in,
                              void* d_out, int out_size) {
    const float* z_what      = (const float*)d_in[0];
    const float* z_pres_prob = (const float*)d_in[1];
    const float* z_pres      = (const float*)d_in[2];
    const float* base_losses = (const float*)d_in[3];
    const void*  gstep       = d_in[4];

    const size_t SMEM = (size_t)2 * NN * PADH * sizeof(half)
                      + (size_t)(2 * NN + 40) * sizeof(float);   // ~43.2 KB
    losses_kernel<<<(TT - 1) * BB, 256, SMEM>>>(z_what, z_pres_prob, z_pres,
                                                base_losses, gstep,
                                                (float*)d_out, out_size);
}

// round 5
// speedup vs baseline: 1.9029x; 1.0027x over previous
#include <cuda_runtime.h>
#include <cuda_fp16.h>

// Fixed problem shapes
#define TT 4
#define BB 512
#define GG 16
#define NN 256
#define DD 32
#define PADH 40          // halves per smem row (80B): conflict-free .128 row access
#define NEG_BIG_F (-1e30f)

__device__ double g_acc[5];        // zwl, zpl, pl(sum cos*w), ol, nobj
__device__ unsigned int g_count;   // zero-init; reset by last block each replay

__device__ __forceinline__ unsigned h2u(half2 h) { return *reinterpret_cast<unsigned*>(&h); }
__device__ __forceinline__ half2    u2h(unsigned u) { return *reinterpret_cast<half2*>(&u); }
__device__ __forceinline__ float    hsumf(half2 h) { float2 f = __half22float2(h); return f.x + f.y; }

__global__ __launch_bounds__(256, 5) void losses_kernel(
    const float* __restrict__ z_what,
    const float* __restrict__ z_pres_prob,
    const float* __restrict__ z_pres,
    const float* __restrict__ base_losses,
    const void*  __restrict__ step_ptr,
    float* __restrict__ out, int out_size)
{
    const int blk = blockIdx.x;
    const int t = blk >> 9;            // / BB
    const int b = blk & (BB - 1);
    const int tid = threadIdx.x;
    const int n   = tid;               // one thread per grid cell
    const int i   = n >> 4, j = n & 15;

    extern __shared__ char smraw[];
    half*  s_wa = (half*)smraw;                     // [NN][PADH] z_what @ t (fp16) -> aliased as hmax
    half*  s_wb = s_wa + NN * PADH;                 // [NN][PADH] z_what @ t+1 (fp16)
    float* s_pb = (float*)(smraw + (size_t)2 * NN * PADH * sizeof(half));
    float* s_nb = s_pb + NN;                        // ||z_what[t+1][m]||
    float* s_red = s_nb + NN;                       // 40 floats

    const size_t slice = (size_t)NN * DD;
    const float4* ga4 = (const float4*)(z_what + ((size_t)t * BB + b) * slice);
    const float4* gb4 = (const float4*)((const float*)ga4 + (size_t)BB * slice);

    // ---- coalesced global load; zwl in fp32 (exact); stage fp16 transposed rows ----
    float zwl = 0.f;
    #pragma unroll
    for (int it = 0; it < 8; ++it) {
        int k4 = it * 256 + tid;
        float4 va = ga4[k4];
        float4 vb = gb4[k4];
        int nn = k4 >> 3;
        int d0 = (k4 & 7) * 4;
        float dx = vb.x - va.x, dy = vb.y - va.y, dz = vb.z - va.z, dw = vb.w - va.w;
        zwl += dx*dx + dy*dy + dz*dz + dw*dw;
        half2 a0 = __floats2half2_rn(va.x, va.y), a1 = __floats2half2_rn(va.z, va.w);
        half2 b0 = __floats2half2_rn(vb.x, vb.y), b1 = __floats2half2_rn(vb.z, vb.w);
        *(uint2*)(s_wa + nn * PADH + d0) = make_uint2(h2u(a0), h2u(a1));
        *(uint2*)(s_wb + nn * PADH + d0) = make_uint2(h2u(b0), h2u(b1));
    }
    const float pa_n = z_pres_prob[((size_t)t * BB + b) * NN + n];
    const float pb_n = z_pres_prob[((size_t)(t + 1) * BB + b) * NN + n];
    s_pb[n] = pb_n;

    // ---- z_pres loss (t = 0,1 windows only), overlap with barrier ----
    float zpl = 0.f;
    if (t < TT - 2) {
        const float* zp = z_pres + ((size_t)t * BB + b) * NN + n;
        float p0 = zp[0];
        float p1 = zp[(size_t)BB * NN];
        float p2 = zp[2 * (size_t)BB * NN];
        float sim = 1.f - (p2 - p0) * (p2 - p0);
        float del = (p2 - p1) * (p2 - p1) + (p0 - p1) * (p0 - p1);
        zpl = sim * del;
    }
    __syncthreads();

    // ---- own rows: pr2 regs; pn2/nb2/dotc via HFMA2 ----
    half2 pr2[16];
    half2 pn2h = __float2half2_rn(0.f), nb2h = pn2h, dotch = pn2h;
    {
        const uint4* ra = (const uint4*)(s_wa + n * PADH);
        const uint4* rb = (const uint4*)(s_wb + n * PADH);
        #pragma unroll
        for (int k = 0; k < 4; ++k) {
            uint4 qa = ra[k], qb = rb[k];
            unsigned ua[4] = {qa.x, qa.y, qa.z, qa.w};
            unsigned ub[4] = {qb.x, qb.y, qb.z, qb.w};
            #pragma unroll
            for (int c = 0; c < 4; ++c) {
                half2 ha = u2h(ua[c]);
                half2 hb = u2h(ub[c]);
                pr2[4 * k + c] = ha;
                pn2h  = __hfma2(ha, ha, pn2h);
                nb2h  = __hfma2(hb, hb, nb2h);
                dotch = __hfma2(ha, hb, dotch);
            }
        }
    }
    const float nbn = sqrtf(hsumf(nb2h));
    const float prior_n = sqrtf(hsumf(pn2h));
    const float dotc = hsumf(dotch);
    s_nb[n] = nbn;

    // ---- pool pass 1: horizontal 3-max of |pr|*pa in half2, own row overwrite ----
    {
        const half2 pa2 = __float2half2_rn(pa_n);
        const bool lok = (j > 0), rok = (j < 15);
        uint4* rowh = (uint4*)(s_wa + n * PADH);
        #pragma unroll
        for (int k4o = 0; k4o < 4; ++k4o) {
            unsigned hv[4];
            #pragma unroll
            for (int c = 0; c < 4; ++c) {
                half2 wv = __hmul2(__habs2(pr2[4 * k4o + c]), pa2);
                unsigned w = h2u(wv);
                unsigned l = __shfl_up_sync(0xffffffffu, w, 1);
                unsigned r = __shfl_down_sync(0xffffffffu, w, 1);
                half2 hm = wv;
                if (lok) hm = __hmax2(hm, u2h(l));
                if (rok) hm = __hmax2(hm, u2h(r));
                hv[c] = h2u(hm);
            }
            rowh[k4o] = make_uint4(hv[0], hv[1], hv[2], hv[3]);
        }
    }
    __syncthreads();

    // ---- pool pass 2: vertical 3-max + cosine parts, all HFMA2 ----
    half2 dotph = __float2half2_rn(0.f), na2h = dotph;
    {
        const uint4* r0 = (const uint4*)(s_wa + n * PADH);
        const uint4* ru = (i > 0)  ? (const uint4*)(s_wa + (n - 16) * PADH) : r0;
        const uint4* rd = (i < 15) ? (const uint4*)(s_wa + (n + 16) * PADH) : r0;
        const uint4* rb = (const uint4*)(s_wb + n * PADH);
        #pragma unroll
        for (int k = 0; k < 4; ++k) {
            uint4 q0 = r0[k], qu = ru[k], qd = rd[k], qb = rb[k];
            unsigned u0[4] = {q0.x, q0.y, q0.z, q0.w};
            unsigned uu[4] = {qu.x, qu.y, qu.z, qu.w};
            unsigned ud[4] = {qd.x, qd.y, qd.z, qd.w};
            unsigned ub[4] = {qb.x, qb.y, qb.z, qb.w};
            #pragma unroll
            for (int c = 0; c < 4; ++c) {
                half2 m  = __hmax2(u2h(u0[c]), __hmax2(u2h(uu[c]), u2h(ud[c])));
                half2 bv = __habs2(u2h(ub[c]));
                dotph = __hfma2(m, bv, dotph);
                na2h  = __hfma2(m, m, na2h);
            }
        }
    }
    float dotp = hsumf(dotph);
    float na2  = hsumf(na2h);
    float cosim = (dotp * pb_n) / fmaxf(sqrtf(na2) * (pb_n * nbn), 1e-6f);
    float plp = cosim * 0.5f * (pa_n + pb_n);     // pool_loss = -sum(plp)

    // ---- objects loss: 9 wrapped-neighbor cosines (center from registers) ----
    float sum_sim = 0.f, max_sim = NEG_BIG_F;
    bool any = false;
    if (pb_n > 0.5f) {
        float s = dotc / fmaxf(prior_n * nbn, 1e-8f);
        sum_sim += s; max_sim = fmaxf(max_sim, s); any = true;
    }
    #pragma unroll
    for (int q = 0; q < 9; ++q) {
        if (q == 4) continue;
        const int di = q / 3 - 1, dj = q % 3 - 1;
        const int m = (((i + di) & 15) << 4) | ((j + dj) & 15);
        if (s_pb[m] > 0.5f) {
            const uint4* rn = (const uint4*)(s_wb + m * PADH);
            half2 dph = __float2half2_rn(0.f);
            #pragma unroll
            for (int k = 0; k < 4; ++k) {
                uint4 qv = rn[k];
                dph = __hfma2(pr2[4*k+0], u2h(qv.x), dph);
                dph = __hfma2(pr2[4*k+1], u2h(qv.y), dph);
                dph = __hfma2(pr2[4*k+2], u2h(qv.z), dph);
                dph = __hfma2(pr2[4*k+3], u2h(qv.w), dph);
            }
            float s = hsumf(dph) / fmaxf(prior_n * s_nb[m], 1e-8f);
            sum_sim += s; max_sim = fmaxf(max_sim, s); any = true;
        }
    }
    bool detected = pa_n > 0.5f;
    float olp  = (detected && any) ? (sum_sim - 5.f * max_sim) : 0.f;
    float nobj = detected ? 1.f : 0.f;

    // ---- block reduce + global accumulate ----
    float vals[5] = {zwl, zpl, plp, olp, nobj};
    #pragma unroll
    for (int k = 0; k < 5; ++k) {
        float v = vals[k];
        #pragma unroll
        for (int o = 16; o > 0; o >>= 1) v += __shfl_down_sync(0xffffffffu, v, o);
        vals[k] = v;
    }
    int lane = tid & 31, w = tid >> 5;
    if (lane == 0) {
        #pragma unroll
        for (int k = 0; k < 5; ++k) s_red[w * 5 + k] = vals[k];
    }
    __syncthreads();
    if (tid == 0) {
        #pragma unroll
        for (int k = 0; k < 5; ++k) {
            float s = 0.f;
            #pragma unroll
            for (int wq = 0; wq < 8; ++wq) s += s_red[wq * 5 + k];
            atomicAdd(&g_acc[k], (double)s);
        }
        __threadfence();
        unsigned ticket = atomicAdd(&g_count, 1u);
        if (ticket == gridDim.x - 1) {
            double a0 = atomicAdd(&g_acc[0], 0.0);
            double a1 = atomicAdd(&g_acc[1], 0.0);
            double a2 = atomicAdd(&g_acc[2], 0.0);
            double a3 = atomicAdd(&g_acc[3], 0.0);
            double a4 = atomicAdd(&g_acc[4], 0.0);
            float zwlT = (float)a0, zplT = (float)a1;
            float plT  = -(float)a2, olT = (float)a3, nobjT = (float)a4;
            float bsum = base_losses[0] + base_losses[1] + base_losses[2] + base_losses[3];
            int iv = *(const int*)step_ptr;
            float gs = (iv >= 0 && iv < 1000000000) ? (float)iv : *(const float*)step_ptr;
            float scaling = fminf(1.f, gs / 300000.f);
            float loss = bsum + zwlT * 10.f + zplT + plT + olT * scaling * 10.f;
            float res[6] = {loss, zwlT, zplT, plT, olT, nobjT};
            for (int k = 0; k < 6 && k < out_size; ++k) out[k] = res[k];
            __threadfence();
            g_acc[0] = 0.0; g_acc[1] = 0.0; g_acc[2] = 0.0;
            g_acc[3] = 0.0; g_acc[4] = 0.0;
            g_count = 0u;
        }
    }
}

extern "C" void kernel_launch(void* const* d_in, const int* in_sizes, int n_in,
                              void* d_out, int out_size) {
    const float* z_what      = (const float*)d_in[0];
    const float* z_pres_prob = (const float*)d_in[1];
    const float* z_pres      = (const float*)d_in[2];
    const float* base_losses = (const float*)d_in[3];
    const void*  gstep       = d_in[4];

    const size_t SMEM = (size_t)2 * NN * PADH * sizeof(half)
                      + (size_t)(2 * NN + 40) * sizeof(float);   // ~43.2 KB
    losses_kernel<<<(TT - 1) * BB, 256, SMEM>>>(z_what, z_pres_prob, z_pres,
                                                base_losses, gstep,
                                                (float*)d_out, out_size);
}

// round 6
// speedup vs baseline: 2.0210x; 1.0621x over previous
#include <cuda_runtime.h>
#include <cuda_fp16.h>

// Fixed problem shapes
#define TT 4
#define BB 512
#define GG 16
#define NN 256
#define DD 32
#define PADH 40          // halves per smem row (80B): conflict-free .128 row access
#define NPAIR ((TT - 1) * BB)   // 1536
#define GRID  740               // 148 SMs x 5 CTAs: one resident wave
#define NEG_BIG_F (-1e30f)

__device__ double g_acc[5];        // zwl, zpl, pl(sum cos*w), ol, nobj
__device__ unsigned int g_count;   // zero-init; reset by last CTA each replay

__device__ __forceinline__ unsigned h2u(half2 h) { return *reinterpret_cast<unsigned*>(&h); }
__device__ __forceinline__ half2    u2h(unsigned u) { return *reinterpret_cast<half2*>(&u); }
__device__ __forceinline__ float    hsumf(half2 h) { float2 f = __half22float2(h); return f.x + f.y; }

__global__ __launch_bounds__(256, 5) void losses_kernel(
    const float* __restrict__ z_what,
    const float* __restrict__ z_pres_prob,
    const float* __restrict__ z_pres,
    const float* __restrict__ base_losses,
    const void*  __restrict__ step_ptr,
    float* __restrict__ out, int out_size)
{
    const int tid = threadIdx.x;
    const int n   = tid;               // one thread per grid cell
    const int i   = n >> 4, j = n & 15;

    extern __shared__ char smraw[];
    half*  s_wa = (half*)smraw;                     // [NN][PADH] z_what @ t -> aliased as hmax
    half*  s_wb = s_wa + NN * PADH;                 // [NN][PADH] z_what @ t+1
    float* s_pb = (float*)(smraw + (size_t)2 * NN * PADH * sizeof(half));
    float* s_nb = s_pb + NN;                        // ||z_what[t+1][m]||
    float* s_red = s_nb + NN;                       // 40 floats

    float acc0 = 0.f, acc1 = 0.f, acc2 = 0.f, acc3 = 0.f, acc4 = 0.f;

    for (int pair = blockIdx.x; pair < NPAIR; pair += GRID) {
        const int t = pair >> 9;           // / BB
        const int b = pair & (BB - 1);

        const size_t slice = (size_t)NN * DD;
        const float4* ga4 = (const float4*)(z_what + ((size_t)t * BB + b) * slice);
        const float4* gb4 = (const float4*)((const float*)ga4 + (size_t)BB * slice);

        // ---- coalesced global load; zwl exact fp32; stage fp16 transposed rows ----
        float zwl = 0.f;
        #pragma unroll
        for (int it = 0; it < 8; ++it) {
            int k4 = it * 256 + tid;
            float4 va = ga4[k4];
            float4 vb = gb4[k4];
            int nn = k4 >> 3;
            int d0 = (k4 & 7) * 4;
            float dx = vb.x - va.x, dy = vb.y - va.y, dz = vb.z - va.z, dw = vb.w - va.w;
            zwl += dx*dx + dy*dy + dz*dz + dw*dw;
            half2 a0 = __floats2half2_rn(va.x, va.y), a1 = __floats2half2_rn(va.z, va.w);
            half2 b0 = __floats2half2_rn(vb.x, vb.y), b1 = __floats2half2_rn(vb.z, vb.w);
            *(uint2*)(s_wa + nn * PADH + d0) = make_uint2(h2u(a0), h2u(a1));
            *(uint2*)(s_wb + nn * PADH + d0) = make_uint2(h2u(b0), h2u(b1));
        }
        acc0 += zwl;
        const float pa_n = z_pres_prob[((size_t)t * BB + b) * NN + n];
        const float pb_n = z_pres_prob[((size_t)(t + 1) * BB + b) * NN + n];
        s_pb[n] = pb_n;

        // ---- z_pres loss (t = 0,1 windows only), overlap with barrier ----
        if (t < TT - 2) {
            const float* zp = z_pres + ((size_t)t * BB + b) * NN + n;
            float p0 = zp[0];
            float p1 = zp[(size_t)BB * NN];
            float p2 = zp[2 * (size_t)BB * NN];
            float sim = 1.f - (p2 - p0) * (p2 - p0);
            float del = (p2 - p1) * (p2 - p1) + (p0 - p1) * (p0 - p1);
            acc1 += sim * del;
        }
        __syncthreads();

        // ---- own rows: pr2 regs; pn2/nb2/dotc via HFMA2 ----
        half2 pr2[16];
        half2 pn2h = __float2half2_rn(0.f), nb2h = pn2h, dotch = pn2h;
        {
            const uint4* ra = (const uint4*)(s_wa + n * PADH);
            const uint4* rb = (const uint4*)(s_wb + n * PADH);
            #pragma unroll
            for (int k = 0; k < 4; ++k) {
                uint4 qa = ra[k], qb = rb[k];
                unsigned ua[4] = {qa.x, qa.y, qa.z, qa.w};
                unsigned ub[4] = {qb.x, qb.y, qb.z, qb.w};
                #pragma unroll
                for (int c = 0; c < 4; ++c) {
                    half2 ha = u2h(ua[c]);
                    half2 hb = u2h(ub[c]);
                    pr2[4 * k + c] = ha;
                    pn2h  = __hfma2(ha, ha, pn2h);
                    nb2h  = __hfma2(hb, hb, nb2h);
                    dotch = __hfma2(ha, hb, dotch);
                }
            }
        }
        const float nbn = sqrtf(hsumf(nb2h));
        const float prior_n = sqrtf(hsumf(pn2h));
        const float dotc = hsumf(dotch);
        s_nb[n] = nbn;

        // ---- pool pass 1: horizontal 3-max of |pr|*pa, own-row overwrite (safe) ----
        {
            const half2 pa2 = __float2half2_rn(pa_n);
            const bool lok = (j > 0), rok = (j < 15);
            uint4* rowh = (uint4*)(s_wa + n * PADH);
            #pragma unroll
            for (int k4o = 0; k4o < 4; ++k4o) {
                unsigned hv[4];
                #pragma unroll
                for (int c = 0; c < 4; ++c) {
                    half2 wv = __hmul2(__habs2(pr2[4 * k4o + c]), pa2);
                    unsigned w = h2u(wv);
                    unsigned l = __shfl_up_sync(0xffffffffu, w, 1);
                    unsigned r = __shfl_down_sync(0xffffffffu, w, 1);
                    half2 hm = wv;
                    if (lok) hm = __hmax2(hm, u2h(l));
                    if (rok) hm = __hmax2(hm, u2h(r));
                    hv[c] = h2u(hm);
                }
                rowh[k4o] = make_uint4(hv[0], hv[1], hv[2], hv[3]);
            }
        }
        __syncthreads();

        // ---- pool pass 2: vertical 3-max + cosine parts (HFMA2) ----
        half2 dotph = __float2half2_rn(0.f), na2h = dotph;
        {
            const uint4* r0 = (const uint4*)(s_wa + n * PADH);
            const uint4* ru = (i > 0)  ? (const uint4*)(s_wa + (n - 16) * PADH) : r0;
            const uint4* rd = (i < 15) ? (const uint4*)(s_wa + (n + 16) * PADH) : r0;
            const uint4* rb = (const uint4*)(s_wb + n * PADH);
            #pragma unroll
            for (int k = 0; k < 4; ++k) {
                uint4 q0 = r0[k], qu = ru[k], qd = rd[k], qb = rb[k];
                unsigned u0[4] = {q0.x, q0.y, q0.z, q0.w};
                unsigned uu[4] = {qu.x, qu.y, qu.z, qu.w};
                unsigned ud[4] = {qd.x, qd.y, qd.z, qd.w};
                unsigned ub[4] = {qb.x, qb.y, qb.z, qb.w};
                #pragma unroll
                for (int c = 0; c < 4; ++c) {
                    half2 m  = __hmax2(u2h(u0[c]), __hmax2(u2h(uu[c]), u2h(ud[c])));
                    half2 bv = __habs2(u2h(ub[c]));
                    dotph = __hfma2(m, bv, dotph);
                    na2h  = __hfma2(m, m, na2h);
                }
            }
        }
        float dotp = hsumf(dotph);
        float na2  = hsumf(na2h);
        float cosim = (dotp * pb_n) / fmaxf(sqrtf(na2) * (pb_n * nbn), 1e-6f);
        acc2 += cosim * 0.5f * (pa_n + pb_n);     // pool_loss = -sum

        // ---- objects loss: 9 wrapped-neighbor cosines (center from regs) ----
        float sum_sim = 0.f, max_sim = NEG_BIG_F;
        bool any = false;
        if (pb_n > 0.5f) {
            float s = dotc / fmaxf(prior_n * nbn, 1e-8f);
            sum_sim += s; max_sim = fmaxf(max_sim, s); any = true;
        }
        #pragma unroll
        for (int q = 0; q < 9; ++q) {
            if (q == 4) continue;
            const int di = q / 3 - 1, dj = q % 3 - 1;
            const int m = (((i + di) & 15) << 4) | ((j + dj) & 15);
            if (s_pb[m] > 0.5f) {
                const uint4* rn = (const uint4*)(s_wb + m * PADH);
                half2 dph = __float2half2_rn(0.f);
                #pragma unroll
                for (int k = 0; k < 4; ++k) {
                    uint4 qv = rn[k];
                    dph = __hfma2(pr2[4*k+0], u2h(qv.x), dph);
                    dph = __hfma2(pr2[4*k+1], u2h(qv.y), dph);
                    dph = __hfma2(pr2[4*k+2], u2h(qv.z), dph);
                    dph = __hfma2(pr2[4*k+3], u2h(qv.w), dph);
                }
                float s = hsumf(dph) / fmaxf(prior_n * s_nb[m], 1e-8f);
                sum_sim += s; max_sim = fmaxf(max_sim, s); any = true;
            }
        }
        bool detected = pa_n > 0.5f;
        if (detected && any) acc3 += sum_sim - 5.f * max_sim;
        if (detected) acc4 += 1.f;

        __syncthreads();   // protect smem before next iteration's staging
    }

    // ---- one block reduction per CTA + global accumulate ----
    float vals[5] = {acc0, acc1, acc2, acc3, acc4};
    #pragma unroll
    for (int k = 0; k < 5; ++k) {
        float v = vals[k];
        #pragma unroll
        for (int o = 16; o > 0; o >>= 1) v += __shfl_down_sync(0xffffffffu, v, o);
        vals[k] = v;
    }
    int lane = tid & 31, w = tid >> 5;
    if (lane == 0) {
        #pragma unroll
        for (int k = 0; k < 5; ++k) s_red[w * 5 + k] = vals[k];
    }
    __syncthreads();
    if (tid == 0) {
        #pragma unroll
        for (int k = 0; k < 5; ++k) {
            float s = 0.f;
            #pragma unroll
            for (int wq = 0; wq < 8; ++wq) s += s_red[wq * 5 + k];
            atomicAdd(&g_acc[k], (double)s);
        }
        __threadfence();
        unsigned ticket = atomicAdd(&g_count, 1u);
        if (ticket == gridDim.x - 1) {
            double a0 = atomicAdd(&g_acc[0], 0.0);
            double a1 = atomicAdd(&g_acc[1], 0.0);
            double a2 = atomicAdd(&g_acc[2], 0.0);
            double a3 = atomicAdd(&g_acc[3], 0.0);
            double a4 = atomicAdd(&g_acc[4], 0.0);
            float zwlT = (float)a0, zplT = (float)a1;
            float plT  = -(float)a2, olT = (float)a3, nobjT = (float)a4;
            float bsum = base_losses[0] + base_losses[1] + base_losses[2] + base_losses[3];
            int iv = *(const int*)step_ptr;
            float gs = (iv >= 0 && iv < 1000000000) ? (float)iv : *(const float*)step_ptr;
            float scaling = fminf(1.f, gs / 300000.f);
            float loss = bsum + zwlT * 10.f + zplT + plT + olT * scaling * 10.f;
            float res[6] = {loss, zwlT, zplT, plT, olT, nobjT};
            for (int k = 0; k < 6 && k < out_size; ++k) out[k] = res[k];
            __threadfence();
            g_acc[0] = 0.0; g_acc[1] = 0.0; g_acc[2] = 0.0;
            g_acc[3] = 0.0; g_acc[4] = 0.0;
            g_count = 0u;
        }
    }
}

extern "C" void kernel_launch(void* const* d_in, const int* in_sizes, int n_in,
                              void* d_out, int out_size) {
    const float* z_what      = (const float*)d_in[0];
    const float* z_pres_prob = (const float*)d_in[1];
    const float* z_pres      = (const float*)d_in[2];
    const float* base_losses = (const float*)d_in[3];
    const void*  gstep       = d_in[4];

    const size_t SMEM = (size_t)2 * NN * PADH * sizeof(half)
                      + (size_t)(2 * NN + 40) * sizeof(float);   // ~43.2 KB
    losses_kernel<<<GRID, 256, SMEM>>>(z_what, z_pres_prob, z_pres,
                                       base_losses, gstep,
                                       (float*)d_out, out_size);
}